// round 5
// baseline (speedup 1.0000x reference)
#include <cuda_runtime.h>
#include <cuda_bf16.h>

// Problem constants
#define NTOT 10000
#define BB   4096
#define DD   512

// -------- scratch (device globals; no allocation allowed) --------
__device__ int   g_counts[NTOT];
__device__ int   g_offsets[NTOT];
__device__ int   g_perm[BB];
__device__ int   g_sidx[BB];
__device__ float g_sq[BB];
__device__ float g_msepart[BB];
__device__ float g_partM[1024];
__device__ float g_partC[1024];
__device__ __align__(16) __nv_bfloat16 g_Yb[(size_t)BB * DD];

// ================= K0: zero histogram =================
__global__ void k_zero() {
    int i = blockIdx.x * blockDim.x + threadIdx.x;
    if (i < NTOT) g_counts[i] = 0;
}

// ================= K1: histogram of idx =================
__global__ void k_hist(const int* __restrict__ idx) {
    int i = blockIdx.x * blockDim.x + threadIdx.x;
    if (i < BB) atomicAdd(&g_counts[idx[i]], 1);
}

// ================= K2: exclusive scan over 10000 counts (1 block) =================
__global__ void k_scan() {
    __shared__ int s[1024];
    int t = threadIdx.x;
    int base = t * 10;
    int c[10];
    int sum = 0;
#pragma unroll
    for (int k = 0; k < 10; k++) {
        int v = (base + k < NTOT) ? g_counts[base + k] : 0;
        c[k] = v; sum += v;
    }
    s[t] = sum;
    __syncthreads();
    for (int off = 1; off < 1024; off <<= 1) {
        int v = (t >= off) ? s[t - off] : 0;
        __syncthreads();
        s[t] += v;
        __syncthreads();
    }
    int run = s[t] - sum;  // exclusive base of this chunk
#pragma unroll
    for (int k = 0; k < 10; k++) {
        if (base + k < NTOT) g_offsets[base + k] = run;
        run += c[k];
    }
}

// ================= K3: stable scatter (deterministic counting sort) =================
__global__ void k_scatter(const int* __restrict__ idx) {
    __shared__ int sh[BB];
    for (int j = threadIdx.x; j < BB; j += blockDim.x) sh[j] = idx[j];
    __syncthreads();
    int i = blockIdx.x * blockDim.x + threadIdx.x;
    if (i >= BB) return;
    int u = sh[i];
    int rank = 0;
    // all lanes step j together -> smem broadcast, conflict-free
    for (int j = 0; j < i; j++) rank += (sh[j] == u);
    int pos = g_offsets[u] + rank;
    g_perm[pos] = i;
    g_sidx[pos] = u;
}

// ================= K4: permute Y -> bf16, row sqnorm (fp32), MSE partials =================
__global__ void k_prep(const float* __restrict__ yp, const float* __restrict__ yt) {
    int r = blockIdx.x;        // sorted row
    int t = threadIdx.x;       // 128 threads, 4 cols each
    int i = g_perm[r];
    const float4* a4 = (const float4*)(yp + (size_t)i * DD);
    const float4* b4 = (const float4*)(yt + (size_t)i * DD);
    float4 a = a4[t];
    float4 b = b4[t];
    float sq = a.x * a.x + a.y * a.y + a.z * a.z + a.w * a.w;
    float dx = a.x - b.x, dy = a.y - b.y, dz = a.z - b.z, dw = a.w - b.w;
    float ms = dx * dx + dy * dy + dz * dz + dw * dw;

    __nv_bfloat162 p0 = __floats2bfloat162_rn(a.x, a.y);
    __nv_bfloat162 p1 = __floats2bfloat162_rn(a.z, a.w);
    __nv_bfloat162* out = (__nv_bfloat162*)(g_Yb + (size_t)r * DD);
    out[2 * t]     = p0;
    out[2 * t + 1] = p1;

#pragma unroll
    for (int off = 16; off; off >>= 1) {
        sq += __shfl_down_sync(0xffffffffu, sq, off);
        ms += __shfl_down_sync(0xffffffffu, ms, off);
    }
    __shared__ float ssq[4], sms[4];
    int w = t >> 5, l = t & 31;
    if (l == 0) { ssq[w] = sq; sms[w] = ms; }
    __syncthreads();
    if (t == 0) {
        g_sq[r]      = ssq[0] + ssq[1] + ssq[2] + ssq[3];
        g_msepart[r] = sms[0] + sms[1] + sms[2] + sms[3];
    }
}

// ================= K5: fused Gram (bf16 mma.sync) + double gather epilogue =================
#define TM 128
#define TN 128
#define TK 32

__device__ __forceinline__ void ldm_x4(unsigned r[4], unsigned addr) {
    asm volatile("ldmatrix.sync.aligned.m8n8.x4.shared.b16 {%0,%1,%2,%3}, [%4];"
                 : "=r"(r[0]), "=r"(r[1]), "=r"(r[2]), "=r"(r[3])
                 : "r"(addr));
}
__device__ __forceinline__ void mma16816(float c[4], const unsigned a[4],
                                         unsigned b0, unsigned b1) {
    asm volatile(
        "mma.sync.aligned.m16n8k16.row.col.f32.bf16.bf16.f32 "
        "{%0,%1,%2,%3}, {%4,%5,%6,%7}, {%8,%9}, {%0,%1,%2,%3};"
        : "+f"(c[0]), "+f"(c[1]), "+f"(c[2]), "+f"(c[3])
        : "r"(a[0]), "r"(a[1]), "r"(a[2]), "r"(a[3]), "r"(b0), "r"(b1));
}

__global__ __launch_bounds__(256, 2) void k_main(const float* __restrict__ ML,
                                                 const float* __restrict__ CL) {
    __shared__ __align__(16) __nv_bfloat16 sA[TM * TK];
    __shared__ __align__(16) __nv_bfloat16 sB[TN * TK];
    __shared__ int   sIu[TM];
    __shared__ int   sJu[TN];
    __shared__ float sSq[TM];
    __shared__ float rM[8], rC[8];

    int tid = threadIdx.x;
    int Ib = blockIdx.y * TM;
    int Jb = blockIdx.x * TN;

    if (tid < TM) {
        sIu[tid] = g_sidx[Ib + tid];
        sSq[tid] = g_sq[Ib + tid];
    } else {
        int t2 = tid - TM;
        sJu[t2] = g_sidx[Jb + t2];
    }

    int wid = tid >> 5, lane = tid & 31;
    int wm = wid & 1;    // 0..1 -> 64 rows each
    int wn = wid >> 1;   // 0..3 -> 32 cols each

    float acc[4][4][4];
#pragma unroll
    for (int a = 0; a < 4; a++)
#pragma unroll
        for (int b = 0; b < 4; b++)
#pragma unroll
            for (int c = 0; c < 4; c++) acc[a][b][c] = 0.f;

    unsigned aBase = (unsigned)__cvta_generic_to_shared(sA);
    unsigned bBase = (unsigned)__cvta_generic_to_shared(sB);

    int lr = tid >> 2;  // 0..63
    int lc = tid & 3;   // 16B chunk within 64B row

    for (int kk = 0; kk < DD; kk += TK) {
        // ---- load A (rows Ib..) and B (rows Jb..) 128x32 bf16, swizzled ----
#pragma unroll
        for (int h = 0; h < 2; h++) {
            int r = lr + h * 64;
            int pc = lc ^ ((r >> 1) & 3);
            ((uint4*)sA)[r * 4 + pc] =
                *(const uint4*)(g_Yb + (size_t)(Ib + r) * DD + kk + lc * 8);
            ((uint4*)sB)[r * 4 + pc] =
                *(const uint4*)(g_Yb + (size_t)(Jb + r) * DD + kk + lc * 8);
        }
        __syncthreads();

#pragma unroll
        for (int ks = 0; ks < 2; ks++) {
            unsigned af[4][4], bf[2][4];
            int chunk = ks * 2 + (lane >> 4);
#pragma unroll
            for (int ma = 0; ma < 4; ma++) {
                int row = wm * 64 + ma * 16 + (lane & 15);
                int pc = chunk ^ ((row >> 1) & 3);
                ldm_x4(af[ma], aBase + (unsigned)(row * 4 + pc) * 16u);
            }
#pragma unroll
            for (int nb = 0; nb < 2; nb++) {
                int row = wn * 32 + nb * 16 + (lane & 15);
                int pc = chunk ^ ((row >> 1) & 3);
                ldm_x4(bf[nb], bBase + (unsigned)(row * 4 + pc) * 16u);
            }
#pragma unroll
            for (int ma = 0; ma < 4; ma++)
#pragma unroll
                for (int na = 0; na < 4; na++) {
                    unsigned b0 = bf[na >> 1][(na & 1)];       // k 0-7
                    unsigned b1 = bf[na >> 1][(na & 1) + 2];   // k 8-15
                    mma16816(acc[ma][na], af[ma], b0, b1);
                }
        }
        __syncthreads();
    }

    // ---- epilogue: gather both link matrices at fragment coords ----
    float aM = 0.f, aC = 0.f;
    int g = lane >> 2, tq = lane & 3;
#pragma unroll
    for (int ma = 0; ma < 4; ma++) {
        int r0 = wm * 64 + ma * 16 + g;
        int r1 = r0 + 8;
        size_t mi0 = (size_t)sIu[r0] * NTOT;
        size_t mi1 = (size_t)sIu[r1] * NTOT;
        float sq0 = sSq[r0], sq1 = sSq[r1];
#pragma unroll
        for (int na = 0; na < 4; na++) {
            int c0 = wn * 32 + na * 8 + tq * 2;
            int u0 = sJu[c0], u1 = sJu[c0 + 1];
            float m00 = __ldg(ML + mi0 + u0);
            float m01 = __ldg(ML + mi0 + u1);
            float m10 = __ldg(ML + mi1 + u0);
            float m11 = __ldg(ML + mi1 + u1);
            float q00 = __ldg(CL + mi0 + u0);
            float q01 = __ldg(CL + mi0 + u1);
            float q10 = __ldg(CL + mi1 + u0);
            float q11 = __ldg(CL + mi1 + u1);
            float d0 = sq0 - acc[ma][na][0];
            float d1 = sq0 - acc[ma][na][1];
            float d2 = sq1 - acc[ma][na][2];
            float d3 = sq1 - acc[ma][na][3];
            aM += m00 * d0 + m01 * d1 + m10 * d2 + m11 * d3;
            aC += q00 * d0 + q01 * d1 + q10 * d2 + q11 * d3;
        }
    }
#pragma unroll
    for (int off = 16; off; off >>= 1) {
        aM += __shfl_down_sync(0xffffffffu, aM, off);
        aC += __shfl_down_sync(0xffffffffu, aC, off);
    }
    if (lane == 0) { rM[wid] = aM; rC[wid] = aC; }
    __syncthreads();
    if (tid == 0) {
        float tM = 0.f, tC = 0.f;
#pragma unroll
        for (int w = 0; w < 8; w++) { tM += rM[w]; tC += rC[w]; }
        int bid = blockIdx.y * gridDim.x + blockIdx.x;
        g_partM[bid] = tM;
        g_partC[bid] = tC;
    }
}

// ================= K6: deterministic final reduce =================
__global__ void k_final(float* out, int out_size) {
    int t = threadIdx.x;  // 1024
    double m = (double)g_partM[t];
    double c = (double)g_partC[t];
    double e = 0.0;
#pragma unroll
    for (int k = 0; k < 4; k++) e += (double)g_msepart[t + k * 1024];
#pragma unroll
    for (int off = 16; off; off >>= 1) {
        m += __shfl_down_sync(0xffffffffu, m, off);
        c += __shfl_down_sync(0xffffffffu, c, off);
        e += __shfl_down_sync(0xffffffffu, e, off);
    }
    __shared__ double sm[32], sc[32], se[32];
    int w = t >> 5, l = t & 31;
    if (l == 0) { sm[w] = m; sc[w] = c; se[w] = e; }
    __syncthreads();
    if (t == 0) {
        double M = 0.0, C = 0.0, E = 0.0;
        for (int i = 0; i < 32; i++) { M += sm[i]; C += sc[i]; E += se[i]; }
        double mse = E / ((double)BB * (double)DD);
        double lml = M * 2.0 / ((double)BB * (double)BB);
        double lcl = C * 2.0 / ((double)BB * (double)BB);
        if (out_size > 0) out[0] = (float)(mse + 0.5 * lml - 0.5 * lcl);
        if (out_size > 1) out[1] = (float)lml;
        if (out_size > 2) out[2] = (float)lcl;
    }
}

// ================= launch =================
extern "C" void kernel_launch(void* const* d_in, const int* in_sizes, int n_in,
                              void* d_out, int out_size) {
    const float* yp = (const float*)d_in[0];
    const float* yt = (const float*)d_in[1];
    const int*   ix = (const int*)d_in[2];
    const float* ml = (const float*)d_in[3];
    const float* cl = (const float*)d_in[4];
    (void)in_sizes; (void)n_in;

    k_zero<<<(NTOT + 255) / 256, 256>>>();
    k_hist<<<BB / 256, 256>>>(ix);
    k_scan<<<1, 1024>>>();
    k_scatter<<<BB / 256, 256>>>(ix);
    k_prep<<<BB, 128>>>(yp, yt);
    k_main<<<dim3(BB / TN, BB / TM), 256>>>(ml, cl);
    k_final<<<1, 1024>>>((float*)d_out, out_size);
}

// round 6
// speedup vs baseline: 1.3573x; 1.3573x over previous
#include <cuda_runtime.h>
#include <cuda_bf16.h>

// Problem constants
#define NTOT 10000
#define BB   4096
#define DD   512

// -------- scratch (device globals; no allocation allowed) --------
__device__ int   g_counts[NTOT];
__device__ int   g_offsets[NTOT];
__device__ int   g_cursor[NTOT];
__device__ int   g_perm[BB];
__device__ int   g_sidx[BB];
__device__ float g_sq[BB];
__device__ float g_msepart[BB];
__device__ float g_partM[1024];
__device__ float g_partC[1024];
__device__ __align__(16) __nv_bfloat16 g_Yb[(size_t)BB * DD];

// ================= K0: zero histogram =================
__global__ void k_zero() {
    int i = blockIdx.x * blockDim.x + threadIdx.x;
    if (i < NTOT) g_counts[i] = 0;
}

// ================= K1: histogram of idx =================
__global__ void k_hist(const int* __restrict__ idx) {
    int i = blockIdx.x * blockDim.x + threadIdx.x;
    if (i < BB) atomicAdd(&g_counts[idx[i]], 1);
}

// ================= K2: exclusive scan over 10000 counts (1 block) =================
__global__ void k_scan() {
    __shared__ int s[1024];
    int t = threadIdx.x;
    int base = t * 10;
    int c[10];
    int sum = 0;
#pragma unroll
    for (int k = 0; k < 10; k++) {
        int v = (base + k < NTOT) ? g_counts[base + k] : 0;
        c[k] = v; sum += v;
    }
    s[t] = sum;
    __syncthreads();
    for (int off = 1; off < 1024; off <<= 1) {
        int v = (t >= off) ? s[t - off] : 0;
        __syncthreads();
        s[t] += v;
        __syncthreads();
    }
    int run = s[t] - sum;  // exclusive base of this chunk
#pragma unroll
    for (int k = 0; k < 10; k++) {
        if (base + k < NTOT) { g_offsets[base + k] = run; g_cursor[base + k] = run; }
        run += c[k];
    }
}

// ================= K3a: atomic scatter (positions within segment unstable) =====
__global__ void k_scatter2(const int* __restrict__ idx) {
    int i = blockIdx.x * blockDim.x + threadIdx.x;
    if (i >= BB) return;
    int u = idx[i];
    int pos = atomicAdd(&g_cursor[u], 1);
    g_perm[pos] = i;
    g_sidx[pos] = u;  // same u anywhere in segment -> order-independent
}

// ================= K3b: per-value segment sort -> fully deterministic perm =====
__global__ void k_sortseg() {
    int u = blockIdx.x * blockDim.x + threadIdx.x;
    if (u >= NTOT) return;
    int n = g_counts[u];
    if (n < 2) return;
    int s = g_offsets[u];
    for (int a = 1; a < n; a++) {           // tiny segments (avg 0.4, max ~6)
        int key = g_perm[s + a];
        int b = a - 1;
        while (b >= 0 && g_perm[s + b] > key) { g_perm[s + b + 1] = g_perm[s + b]; b--; }
        g_perm[s + b + 1] = key;
    }
}

// ================= K4: permute Y -> bf16, row sqnorm (fp32), MSE partials =================
__global__ void k_prep(const float* __restrict__ yp, const float* __restrict__ yt) {
    int r = blockIdx.x;        // sorted row
    int t = threadIdx.x;       // 128 threads, 4 cols each
    int i = g_perm[r];
    const float4* a4 = (const float4*)(yp + (size_t)i * DD);
    const float4* b4 = (const float4*)(yt + (size_t)i * DD);
    float4 a = a4[t];
    float4 b = b4[t];
    float sq = a.x * a.x + a.y * a.y + a.z * a.z + a.w * a.w;
    float dx = a.x - b.x, dy = a.y - b.y, dz = a.z - b.z, dw = a.w - b.w;
    float ms = dx * dx + dy * dy + dz * dz + dw * dw;

    __nv_bfloat162 p0 = __floats2bfloat162_rn(a.x, a.y);
    __nv_bfloat162 p1 = __floats2bfloat162_rn(a.z, a.w);
    __nv_bfloat162* out = (__nv_bfloat162*)(g_Yb + (size_t)r * DD);
    out[2 * t]     = p0;
    out[2 * t + 1] = p1;

#pragma unroll
    for (int off = 16; off; off >>= 1) {
        sq += __shfl_down_sync(0xffffffffu, sq, off);
        ms += __shfl_down_sync(0xffffffffu, ms, off);
    }
    __shared__ float ssq[4], sms[4];
    int w = t >> 5, l = t & 31;
    if (l == 0) { ssq[w] = sq; sms[w] = ms; }
    __syncthreads();
    if (t == 0) {
        g_sq[r]      = ssq[0] + ssq[1] + ssq[2] + ssq[3];
        g_msepart[r] = sms[0] + sms[1] + sms[2] + sms[3];
    }
}

// ================= K5: fused Gram (bf16 mma) + pipelined coalesced gather ======
#define TM 128
#define TN 128
#define TK 32

// dynamic smem layout (bytes)
#define SA_OFF   0            // 2 stages x 8192
#define SB_OFF   16384        // 2 stages x 8192
#define SM_OFF   32768        // 128 x 136 bf16 = 34816
#define SC_OFF   67584        // 128 x 136 bf16 = 34816
#define SIU_OFF  102400       // 128 int
#define SJU_OFF  102912       // 128 int
#define SSQ_OFF  103424       // 128 float
#define RED_OFF  103936       // 16 float
#define SMEM_BYTES 104064
#define SMP 68                // sM/sC row pitch in 32-bit words (136 bf16)

__device__ __forceinline__ void ldm_x4(unsigned r[4], unsigned addr) {
    asm volatile("ldmatrix.sync.aligned.m8n8.x4.shared.b16 {%0,%1,%2,%3}, [%4];"
                 : "=r"(r[0]), "=r"(r[1]), "=r"(r[2]), "=r"(r[3])
                 : "r"(addr));
}
__device__ __forceinline__ void mma16816(float c[4], const unsigned a[4],
                                         unsigned b0, unsigned b1) {
    asm volatile(
        "mma.sync.aligned.m16n8k16.row.col.f32.bf16.bf16.f32 "
        "{%0,%1,%2,%3}, {%4,%5,%6,%7}, {%8,%9}, {%0,%1,%2,%3};"
        : "+f"(c[0]), "+f"(c[1]), "+f"(c[2]), "+f"(c[3])
        : "r"(a[0]), "r"(a[1]), "r"(a[2]), "r"(a[3]), "r"(b0), "r"(b1));
}
__device__ __forceinline__ void cp16(unsigned saddr, const void* g) {
    asm volatile("cp.async.cg.shared.global [%0], [%1], 16;" :: "r"(saddr), "l"(g));
}
__device__ __forceinline__ void cp_commit() {
    asm volatile("cp.async.commit_group;");
}
template <int N> __device__ __forceinline__ void cp_wait() {
    asm volatile("cp.async.wait_group %0;" :: "n"(N));
}

__global__ __launch_bounds__(256, 2) void k_main(const float* __restrict__ ML,
                                                 const float* __restrict__ CL) {
    extern __shared__ __align__(16) char dsm[];
    unsigned sbase = (unsigned)__cvta_generic_to_shared(dsm);
    int*      sIu = (int*)(dsm + SIU_OFF);
    int*      sJu = (int*)(dsm + SJU_OFF);
    float*    sSq = (float*)(dsm + SSQ_OFF);
    float*    rM  = (float*)(dsm + RED_OFF);
    float*    rC  = rM + 8;
    unsigned* sMu = (unsigned*)(dsm + SM_OFF);   // bf16x2 words, pitch SMP
    unsigned* sCu = (unsigned*)(dsm + SC_OFF);

    int tid = threadIdx.x;
    int Ib = blockIdx.y * TM;
    int Jb = blockIdx.x * TN;

    if (tid < TM) {
        sIu[tid] = g_sidx[Ib + tid];
        sSq[tid] = g_sq[Ib + tid];
    } else {
        sJu[tid - TM] = g_sidx[Jb + tid - TM];
    }

    int wid = tid >> 5, lane = tid & 31;
    int wm = wid & 1;    // 0..1 -> 64 rows each
    int wn = wid >> 1;   // 0..3 -> 32 cols each

    float acc[4][4][4];
#pragma unroll
    for (int a = 0; a < 4; a++)
#pragma unroll
        for (int b = 0; b < 4; b++)
#pragma unroll
            for (int c = 0; c < 4; c++) acc[a][b][c] = 0.f;

    int lr = tid >> 2;  // 0..63
    int lc = tid & 3;   // 16B chunk within 64B row

    // -------- stage loader (cp.async) --------
    auto loadstage = [&](int it, int st) {
        int kk = it * TK;
        unsigned aS = sbase + SA_OFF + st * 8192;
        unsigned bS = sbase + SB_OFF + st * 8192;
#pragma unroll
        for (int h = 0; h < 2; h++) {
            int r = lr + h * 64;
            int pc = lc ^ ((r >> 1) & 3);
            cp16(aS + (unsigned)(r * 4 + pc) * 16u,
                 g_Yb + (size_t)(Ib + r) * DD + kk + lc * 8);
            cp16(bS + (unsigned)(r * 4 + pc) * 16u,
                 g_Yb + (size_t)(Jb + r) * DD + kk + lc * 8);
        }
        cp_commit();
    };

    loadstage(0, 0);

    for (int it = 0; it < 16; it++) {
        int st = it & 1;
        __syncthreads();                       // prior-iter smem reads done
        if (it < 15) { loadstage(it + 1, st ^ 1); cp_wait<1>(); }
        else         { cp_wait<0>(); }
        __syncthreads();                       // current stage visible to all

        // ---- issue gather loads (coalesced: lanes = consecutive sorted cols) ----
        float mv[4], cv[4];
        int gr[2], gc[2];
#pragma unroll
        for (int q = 0; q < 2; q++) {
            int p = (it * 2 + q) * 256 + tid;
            int r = p >> 6, c2 = p & 63, c = c2 * 2;
            gr[q] = r; gc[q] = c2;
            size_t rowo = (size_t)sIu[r] * NTOT;
            int u0 = sJu[c], u1 = sJu[c + 1];
            mv[2 * q]     = __ldg(ML + rowo + u0);
            mv[2 * q + 1] = __ldg(ML + rowo + u1);
            cv[2 * q]     = __ldg(CL + rowo + u0);
            cv[2 * q + 1] = __ldg(CL + rowo + u1);
        }

        // ---- MMA on stage st (gather loads in flight) ----
        unsigned aBase = sbase + SA_OFF + st * 8192;
        unsigned bBase = sbase + SB_OFF + st * 8192;
#pragma unroll
        for (int ks = 0; ks < 2; ks++) {
            unsigned af[4][4], bf[2][4];
            int chunk = ks * 2 + (lane >> 4);
#pragma unroll
            for (int ma = 0; ma < 4; ma++) {
                int row = wm * 64 + ma * 16 + (lane & 15);
                int pc = chunk ^ ((row >> 1) & 3);
                ldm_x4(af[ma], aBase + (unsigned)(row * 4 + pc) * 16u);
            }
#pragma unroll
            for (int nb = 0; nb < 2; nb++) {
                int row = wn * 32 + nb * 16 + (lane & 15);
                int pc = chunk ^ ((row >> 1) & 3);
                ldm_x4(bf[nb], bBase + (unsigned)(row * 4 + pc) * 16u);
            }
#pragma unroll
            for (int ma = 0; ma < 4; ma++)
#pragma unroll
                for (int na = 0; na < 4; na++) {
                    unsigned b0 = bf[na >> 1][(na & 1)];
                    unsigned b1 = bf[na >> 1][(na & 1) + 2];
                    mma16816(acc[ma][na], af[ma], b0, b1);
                }
        }

        // ---- stash gathered values (arrived during MMA) ----
#pragma unroll
        for (int q = 0; q < 2; q++) {
            __nv_bfloat162 m2 = __floats2bfloat162_rn(mv[2 * q], mv[2 * q + 1]);
            __nv_bfloat162 c2 = __floats2bfloat162_rn(cv[2 * q], cv[2 * q + 1]);
            sMu[gr[q] * SMP + gc[q]] = *(unsigned*)&m2;
            sCu[gr[q] * SMP + gc[q]] = *(unsigned*)&c2;
        }
    }
    __syncthreads();

    // ---- epilogue: everything from smem, conflict-free ----
    float aM = 0.f, aC = 0.f;
    int g = lane >> 2, tq = lane & 3;
#pragma unroll
    for (int ma = 0; ma < 4; ma++) {
        int r0 = wm * 64 + ma * 16 + g;
        int r1 = r0 + 8;
        float sq0 = sSq[r0], sq1 = sSq[r1];
#pragma unroll
        for (int na = 0; na < 4; na++) {
            int cw = wn * 16 + na * 4 + tq;   // 32-bit word column (= 2 bf16 cols)
            unsigned wm0 = sMu[r0 * SMP + cw];
            unsigned wm1 = sMu[r1 * SMP + cw];
            unsigned wc0 = sCu[r0 * SMP + cw];
            unsigned wc1 = sCu[r1 * SMP + cw];
            float2 fm0 = __bfloat1622float2(*(__nv_bfloat162*)&wm0);
            float2 fm1 = __bfloat1622float2(*(__nv_bfloat162*)&wm1);
            float2 fc0 = __bfloat1622float2(*(__nv_bfloat162*)&wc0);
            float2 fc1 = __bfloat1622float2(*(__nv_bfloat162*)&wc1);
            float d0 = sq0 - acc[ma][na][0];
            float d1 = sq0 - acc[ma][na][1];
            float d2 = sq1 - acc[ma][na][2];
            float d3 = sq1 - acc[ma][na][3];
            aM += fm0.x * d0 + fm0.y * d1 + fm1.x * d2 + fm1.y * d3;
            aC += fc0.x * d0 + fc0.y * d1 + fc1.x * d2 + fc1.y * d3;
        }
    }
#pragma unroll
    for (int off = 16; off; off >>= 1) {
        aM += __shfl_down_sync(0xffffffffu, aM, off);
        aC += __shfl_down_sync(0xffffffffu, aC, off);
    }
    if (lane == 0) { rM[wid] = aM; rC[wid] = aC; }
    __syncthreads();
    if (tid == 0) {
        float tMv = 0.f, tCv = 0.f;
#pragma unroll
        for (int w = 0; w < 8; w++) { tMv += rM[w]; tCv += rC[w]; }
        int bid = blockIdx.y * gridDim.x + blockIdx.x;
        g_partM[bid] = tMv;
        g_partC[bid] = tCv;
    }
}

// ================= K6: deterministic final reduce =================
__global__ void k_final(float* out, int out_size) {
    int t = threadIdx.x;  // 1024
    double m = (double)g_partM[t];
    double c = (double)g_partC[t];
    double e = 0.0;
#pragma unroll
    for (int k = 0; k < 4; k++) e += (double)g_msepart[t + k * 1024];
#pragma unroll
    for (int off = 16; off; off >>= 1) {
        m += __shfl_down_sync(0xffffffffu, m, off);
        c += __shfl_down_sync(0xffffffffu, c, off);
        e += __shfl_down_sync(0xffffffffu, e, off);
    }
    __shared__ double sm[32], sc[32], se[32];
    int w = t >> 5, l = t & 31;
    if (l == 0) { sm[w] = m; sc[w] = c; se[w] = e; }
    __syncthreads();
    if (t == 0) {
        double M = 0.0, C = 0.0, E = 0.0;
        for (int i = 0; i < 32; i++) { M += sm[i]; C += sc[i]; E += se[i]; }
        double mse = E / ((double)BB * (double)DD);
        double lml = M * 2.0 / ((double)BB * (double)BB);
        double lcl = C * 2.0 / ((double)BB * (double)BB);
        if (out_size > 0) out[0] = (float)(mse + 0.5 * lml - 0.5 * lcl);
        if (out_size > 1) out[1] = (float)lml;
        if (out_size > 2) out[2] = (float)lcl;
    }
}

// ================= launch =================
extern "C" void kernel_launch(void* const* d_in, const int* in_sizes, int n_in,
                              void* d_out, int out_size) {
    const float* yp = (const float*)d_in[0];
    const float* yt = (const float*)d_in[1];
    const int*   ix = (const int*)d_in[2];
    const float* ml = (const float*)d_in[3];
    const float* cl = (const float*)d_in[4];
    (void)in_sizes; (void)n_in;

    static bool attr_set = false;
    if (!attr_set) {
        cudaFuncSetAttribute(k_main, cudaFuncAttributeMaxDynamicSharedMemorySize,
                             SMEM_BYTES);
        attr_set = true;
    }

    k_zero<<<(NTOT + 255) / 256, 256>>>();
    k_hist<<<BB / 256, 256>>>(ix);
    k_scan<<<1, 1024>>>();
    k_scatter2<<<BB / 256, 256>>>(ix);
    k_sortseg<<<(NTOT + 255) / 256, 256>>>();
    k_prep<<<BB, 128>>>(yp, yt);
    k_main<<<dim3(BB / TN, BB / TM), 256, SMEM_BYTES>>>(ml, cl);
    k_final<<<1, 1024>>>((float*)d_out, out_size);
}

// round 7
// speedup vs baseline: 1.3576x; 1.0002x over previous
#include <cuda_runtime.h>
#include <cuda_bf16.h>

// Problem constants
#define NTOT 10000
#define BB   4096
#define DD   512

// -------- scratch (device globals; no allocation allowed) --------
__device__ int   g_counts[NTOT];
__device__ int   g_offsets[NTOT];
__device__ int   g_cursor[NTOT];
__device__ int   g_perm[BB];
__device__ int   g_ulist[BB];        // compact sorted unique values (U entries, rest zeroed)
__device__ int   g_U;
__device__ float g_s[BB];            // per-unique sum of ||y_i||^2
__device__ float g_c[BB];            // per-unique count (float)
__device__ float g_msepart[BB];
__device__ float g_partM[1024];
__device__ float g_partC[1024];
__device__ __align__(16) __nv_bfloat16 g_Zb[(size_t)BB * DD];  // aggregated embeddings

// ================= K0: zero histogram =================
__global__ void k_zero() {
    int i = blockIdx.x * blockDim.x + threadIdx.x;
    if (i < NTOT) g_counts[i] = 0;
}

// ================= K1: histogram of idx =================
__global__ void k_hist(const int* __restrict__ idx) {
    int i = blockIdx.x * blockDim.x + threadIdx.x;
    if (i < BB) atomicAdd(&g_counts[idx[i]], 1);
}

// ====== K2: scans — segment offsets AND compact unique list (1 block) ======
__global__ void k_scan() {
    __shared__ int s[1024];
    int t = threadIdx.x;
    int base = t * 10;
    int c[10];
    int sum = 0, usum = 0;
#pragma unroll
    for (int k = 0; k < 10; k++) {
        int v = (base + k < NTOT) ? g_counts[base + k] : 0;
        c[k] = v; sum += v; usum += (v > 0);
    }
    // scan 1: position offsets
    s[t] = sum;
    __syncthreads();
    for (int off = 1; off < 1024; off <<= 1) {
        int v = (t >= off) ? s[t - off] : 0;
        __syncthreads();
        s[t] += v;
        __syncthreads();
    }
    int run = s[t] - sum;
#pragma unroll
    for (int k = 0; k < 10; k++) {
        if (base + k < NTOT) { g_offsets[base + k] = run; g_cursor[base + k] = run; }
        run += c[k];
    }
    __syncthreads();
    // scan 2: unique compaction
    s[t] = usum;
    __syncthreads();
    for (int off = 1; off < 1024; off <<= 1) {
        int v = (t >= off) ? s[t - off] : 0;
        __syncthreads();
        s[t] += v;
        __syncthreads();
    }
    int urun = s[t] - usum;
#pragma unroll
    for (int k = 0; k < 10; k++) {
        if (base + k < NTOT && c[k] > 0) { g_ulist[urun] = base + k; urun++; }
    }
    if (t == 1023) g_U = s[1023];
}

// ================= K3a: atomic scatter =================
__global__ void k_scatter2(const int* __restrict__ idx) {
    int i = blockIdx.x * blockDim.x + threadIdx.x;
    if (i >= BB) return;
    int u = idx[i];
    int pos = atomicAdd(&g_cursor[u], 1);
    g_perm[pos] = i;
}

// ============ K3b: per-value segment sort -> deterministic perm ============
__global__ void k_sortseg() {
    int u = blockIdx.x * blockDim.x + threadIdx.x;
    if (u >= NTOT) return;
    int n = g_counts[u];
    if (n < 2) return;
    int s = g_offsets[u];
    for (int a = 1; a < n; a++) {
        int key = g_perm[s + a];
        int b = a - 1;
        while (b >= 0 && g_perm[s + b] > key) { g_perm[s + b + 1] = g_perm[s + b]; b--; }
        g_perm[s + b + 1] = key;
    }
}

// ================= K4: MSE partials (per original row) =================
__global__ void k_mse(const float* __restrict__ yp, const float* __restrict__ yt) {
    int r = blockIdx.x;
    int t = threadIdx.x;   // 128 threads, 4 cols each
    float4 a = ((const float4*)(yp + (size_t)r * DD))[t];
    float4 b = ((const float4*)(yt + (size_t)r * DD))[t];
    float dx = a.x - b.x, dy = a.y - b.y, dz = a.z - b.z, dw = a.w - b.w;
    float ms = dx * dx + dy * dy + dz * dz + dw * dw;
#pragma unroll
    for (int off = 16; off; off >>= 1)
        ms += __shfl_down_sync(0xffffffffu, ms, off);
    __shared__ float sms[4];
    int w = t >> 5, l = t & 31;
    if (l == 0) sms[w] = ms;
    __syncthreads();
    if (t == 0) g_msepart[r] = sms[0] + sms[1] + sms[2] + sms[3];
}

// ===== K5: per-unique aggregation: Z_u (bf16), s_u, c_u; zero-pad tail =====
__global__ void k_aggr(const float* __restrict__ yp) {
    int k = blockIdx.x;        // 0..BB-1
    int t = threadIdx.x;       // 128 threads, 4 cols each
    int U = g_U;
    __nv_bfloat162* zOut = (__nv_bfloat162*)(g_Zb + (size_t)k * DD);
    if (k >= U) {
        __nv_bfloat162 z2; z2.x = __float2bfloat16(0.f); z2.y = z2.x;
        zOut[2 * t] = z2; zOut[2 * t + 1] = z2;
        if (t == 0) { g_s[k] = 0.f; g_c[k] = 0.f; g_ulist[k] = 0; }
        return;
    }
    int u = g_ulist[k];
    int s0 = g_offsets[u], cnt = g_counts[u];
    float ax = 0.f, ay = 0.f, az = 0.f, aw = 0.f, sq = 0.f;
    for (int a = 0; a < cnt; a++) {          // ordered -> deterministic
        int i = g_perm[s0 + a];
        float4 v = ((const float4*)(yp + (size_t)i * DD))[t];
        ax += v.x; ay += v.y; az += v.z; aw += v.w;
        sq += v.x * v.x + v.y * v.y + v.z * v.z + v.w * v.w;
    }
    zOut[2 * t]     = __floats2bfloat162_rn(ax, ay);
    zOut[2 * t + 1] = __floats2bfloat162_rn(az, aw);
#pragma unroll
    for (int off = 16; off; off >>= 1)
        sq += __shfl_down_sync(0xffffffffu, sq, off);
    __shared__ float ssq[4];
    int w = t >> 5, l = t & 31;
    if (l == 0) ssq[w] = sq;
    __syncthreads();
    if (t == 0) {
        g_s[k] = ssq[0] + ssq[1] + ssq[2] + ssq[3];
        g_c[k] = (float)cnt;
    }
}

// ======= K6: fused Gram (bf16 mma) on unique rows + pipelined gather =======
#define TM 128
#define TN 128
#define TK 32

// dynamic smem layout (bytes)
#define SA_OFF   0            // 2 stages x 8192
#define SB_OFF   16384        // 2 stages x 8192
#define SM_OFF   32768        // 128 x 136 bf16 = 34816
#define SC_OFF   67584        // 128 x 136 bf16 = 34816
#define SIU_OFF  102400       // 128 int  (row ulist)
#define SJU_OFF  102912       // 128 int  (col ulist)
#define SSQ_OFF  103424       // 128 float (row s_u)
#define SCC_OFF  103936       // 128 float (col counts)
#define RED_OFF  104448       // 16 float
#define SMEM_BYTES 104512
#define SMP 68                // sM/sC row pitch in 32-bit words (136 bf16)

__device__ __forceinline__ void ldm_x4(unsigned r[4], unsigned addr) {
    asm volatile("ldmatrix.sync.aligned.m8n8.x4.shared.b16 {%0,%1,%2,%3}, [%4];"
                 : "=r"(r[0]), "=r"(r[1]), "=r"(r[2]), "=r"(r[3])
                 : "r"(addr));
}
__device__ __forceinline__ void mma16816(float c[4], const unsigned a[4],
                                         unsigned b0, unsigned b1) {
    asm volatile(
        "mma.sync.aligned.m16n8k16.row.col.f32.bf16.bf16.f32 "
        "{%0,%1,%2,%3}, {%4,%5,%6,%7}, {%8,%9}, {%0,%1,%2,%3};"
        : "+f"(c[0]), "+f"(c[1]), "+f"(c[2]), "+f"(c[3])
        : "r"(a[0]), "r"(a[1]), "r"(a[2]), "r"(a[3]), "r"(b0), "r"(b1));
}
__device__ __forceinline__ void cp16(unsigned saddr, const void* g) {
    asm volatile("cp.async.cg.shared.global [%0], [%1], 16;" :: "r"(saddr), "l"(g));
}
__device__ __forceinline__ void cp_commit() {
    asm volatile("cp.async.commit_group;");
}
template <int N> __device__ __forceinline__ void cp_wait() {
    asm volatile("cp.async.wait_group %0;" :: "n"(N));
}

__global__ __launch_bounds__(256, 2) void k_main(const float* __restrict__ ML,
                                                 const float* __restrict__ CL) {
    extern __shared__ __align__(16) char dsm[];
    unsigned sbase = (unsigned)__cvta_generic_to_shared(dsm);
    int*      sIu = (int*)(dsm + SIU_OFF);
    int*      sJu = (int*)(dsm + SJU_OFF);
    float*    sSq = (float*)(dsm + SSQ_OFF);
    float*    sCc = (float*)(dsm + SCC_OFF);
    float*    rM  = (float*)(dsm + RED_OFF);
    float*    rC  = rM + 8;
    unsigned* sMu = (unsigned*)(dsm + SM_OFF);   // bf16x2 words, pitch SMP
    unsigned* sCu = (unsigned*)(dsm + SC_OFF);

    int tid = threadIdx.x;
    int Ib = blockIdx.y * TM;
    int Jb = blockIdx.x * TN;
    int bid = blockIdx.y * gridDim.x + blockIdx.x;

    int U = g_U;
    if (Ib >= U || Jb >= U) {                  // tile entirely padding -> zero contribution
        if (tid == 0) { g_partM[bid] = 0.f; g_partC[bid] = 0.f; }
        return;
    }

    if (tid < TM) {
        sIu[tid] = g_ulist[Ib + tid];
        sSq[tid] = g_s[Ib + tid];
    } else {
        sJu[tid - TM] = g_ulist[Jb + tid - TM];
        sCc[tid - TM] = g_c[Jb + tid - TM];
    }

    int wid = tid >> 5, lane = tid & 31;
    int wm = wid & 1;    // 0..1 -> 64 rows each
    int wn = wid >> 1;   // 0..3 -> 32 cols each

    float acc[4][4][4];
#pragma unroll
    for (int a = 0; a < 4; a++)
#pragma unroll
        for (int b = 0; b < 4; b++)
#pragma unroll
            for (int c = 0; c < 4; c++) acc[a][b][c] = 0.f;

    int lr = tid >> 2;  // 0..63
    int lc = tid & 3;   // 16B chunk within 64B row

    auto loadstage = [&](int it, int st) {
        int kk = it * TK;
        unsigned aS = sbase + SA_OFF + st * 8192;
        unsigned bS = sbase + SB_OFF + st * 8192;
#pragma unroll
        for (int h = 0; h < 2; h++) {
            int r = lr + h * 64;
            int pc = lc ^ ((r >> 1) & 3);
            cp16(aS + (unsigned)(r * 4 + pc) * 16u,
                 g_Zb + (size_t)(Ib + r) * DD + kk + lc * 8);
            cp16(bS + (unsigned)(r * 4 + pc) * 16u,
                 g_Zb + (size_t)(Jb + r) * DD + kk + lc * 8);
        }
        cp_commit();
    };

    loadstage(0, 0);

    for (int it = 0; it < 16; it++) {
        int st = it & 1;
        __syncthreads();
        if (it < 15) { loadstage(it + 1, st ^ 1); cp_wait<1>(); }
        else         { cp_wait<0>(); }
        __syncthreads();

        // ---- issue gather loads (coalesced: lanes = consecutive sorted cols) ----
        float mv[4], cv[4];
        int gr[2], gc[2];
#pragma unroll
        for (int q = 0; q < 2; q++) {
            int p = (it * 2 + q) * 256 + tid;
            int r = p >> 6, c2 = p & 63, c = c2 * 2;
            gr[q] = r; gc[q] = c2;
            size_t rowo = (size_t)sIu[r] * NTOT;
            int u0 = sJu[c], u1 = sJu[c + 1];
            mv[2 * q]     = __ldg(ML + rowo + u0);
            mv[2 * q + 1] = __ldg(ML + rowo + u1);
            cv[2 * q]     = __ldg(CL + rowo + u0);
            cv[2 * q + 1] = __ldg(CL + rowo + u1);
        }

        // ---- MMA on stage st (gather loads in flight) ----
        unsigned aBase = sbase + SA_OFF + st * 8192;
        unsigned bBase = sbase + SB_OFF + st * 8192;
#pragma unroll
        for (int ks = 0; ks < 2; ks++) {
            unsigned af[4][4], bf[2][4];
            int chunk = ks * 2 + (lane >> 4);
#pragma unroll
            for (int ma = 0; ma < 4; ma++) {
                int row = wm * 64 + ma * 16 + (lane & 15);
                int pc = chunk ^ ((row >> 1) & 3);
                ldm_x4(af[ma], aBase + (unsigned)(row * 4 + pc) * 16u);
            }
#pragma unroll
            for (int nb = 0; nb < 2; nb++) {
                int row = wn * 32 + nb * 16 + (lane & 15);
                int pc = chunk ^ ((row >> 1) & 3);
                ldm_x4(bf[nb], bBase + (unsigned)(row * 4 + pc) * 16u);
            }
#pragma unroll
            for (int ma = 0; ma < 4; ma++)
#pragma unroll
                for (int na = 0; na < 4; na++) {
                    unsigned b0 = bf[na >> 1][(na & 1)];
                    unsigned b1 = bf[na >> 1][(na & 1) + 2];
                    mma16816(acc[ma][na], af[ma], b0, b1);
                }
        }

        // ---- stash gathered values (arrived during MMA) ----
#pragma unroll
        for (int q = 0; q < 2; q++) {
            __nv_bfloat162 m2 = __floats2bfloat162_rn(mv[2 * q], mv[2 * q + 1]);
            __nv_bfloat162 c2 = __floats2bfloat162_rn(cv[2 * q], cv[2 * q + 1]);
            sMu[gr[q] * SMP + gc[q]] = *(unsigned*)&m2;
            sCu[gr[q] * SMP + gc[q]] = *(unsigned*)&c2;
        }
    }
    __syncthreads();

    // ---- epilogue: d = c_v * s_u - Z_u.Z_v, all operands from smem ----
    float aM = 0.f, aC = 0.f;
    int g = lane >> 2, tq = lane & 3;
#pragma unroll
    for (int ma = 0; ma < 4; ma++) {
        int r0 = wm * 64 + ma * 16 + g;
        int r1 = r0 + 8;
        float sq0 = sSq[r0], sq1 = sSq[r1];
#pragma unroll
        for (int na = 0; na < 4; na++) {
            int cw = wn * 16 + na * 4 + tq;   // 32-bit word column (= 2 bf16 cols)
            float cc0 = sCc[2 * cw], cc1 = sCc[2 * cw + 1];
            unsigned wm0 = sMu[r0 * SMP + cw];
            unsigned wm1 = sMu[r1 * SMP + cw];
            unsigned wc0 = sCu[r0 * SMP + cw];
            unsigned wc1 = sCu[r1 * SMP + cw];
            float2 fm0 = __bfloat1622float2(*(__nv_bfloat162*)&wm0);
            float2 fm1 = __bfloat1622float2(*(__nv_bfloat162*)&wm1);
            float2 fc0 = __bfloat1622float2(*(__nv_bfloat162*)&wc0);
            float2 fc1 = __bfloat1622float2(*(__nv_bfloat162*)&wc1);
            float d0 = cc0 * sq0 - acc[ma][na][0];
            float d1 = cc1 * sq0 - acc[ma][na][1];
            float d2 = cc0 * sq1 - acc[ma][na][2];
            float d3 = cc1 * sq1 - acc[ma][na][3];
            aM += fm0.x * d0 + fm0.y * d1 + fm1.x * d2 + fm1.y * d3;
            aC += fc0.x * d0 + fc0.y * d1 + fc1.x * d2 + fc1.y * d3;
        }
    }
#pragma unroll
    for (int off = 16; off; off >>= 1) {
        aM += __shfl_down_sync(0xffffffffu, aM, off);
        aC += __shfl_down_sync(0xffffffffu, aC, off);
    }
    if (lane == 0) { rM[wid] = aM; rC[wid] = aC; }
    __syncthreads();
    if (tid == 0) {
        float tMv = 0.f, tCv = 0.f;
#pragma unroll
        for (int w = 0; w < 8; w++) { tMv += rM[w]; tCv += rC[w]; }
        g_partM[bid] = tMv;
        g_partC[bid] = tCv;
    }
}

// ================= K7: deterministic final reduce =================
__global__ void k_final(float* out, int out_size) {
    int t = threadIdx.x;  // 1024
    double m = (double)g_partM[t];
    double c = (double)g_partC[t];
    double e = 0.0;
#pragma unroll
    for (int k = 0; k < 4; k++) e += (double)g_msepart[t + k * 1024];
#pragma unroll
    for (int off = 16; off; off >>= 1) {
        m += __shfl_down_sync(0xffffffffu, m, off);
        c += __shfl_down_sync(0xffffffffu, c, off);
        e += __shfl_down_sync(0xffffffffu, e, off);
    }
    __shared__ double sm[32], sc[32], se[32];
    int w = t >> 5, l = t & 31;
    if (l == 0) { sm[w] = m; sc[w] = c; se[w] = e; }
    __syncthreads();
    if (t == 0) {
        double M = 0.0, C = 0.0, E = 0.0;
        for (int i = 0; i < 32; i++) { M += sm[i]; C += sc[i]; E += se[i]; }
        double mse = E / ((double)BB * (double)DD);
        double lml = M * 2.0 / ((double)BB * (double)BB);
        double lcl = C * 2.0 / ((double)BB * (double)BB);
        if (out_size > 0) out[0] = (float)(mse + 0.5 * lml - 0.5 * lcl);
        if (out_size > 1) out[1] = (float)lml;
        if (out_size > 2) out[2] = (float)lcl;
    }
}

// ================= launch =================
extern "C" void kernel_launch(void* const* d_in, const int* in_sizes, int n_in,
                              void* d_out, int out_size) {
    const float* yp = (const float*)d_in[0];
    const float* yt = (const float*)d_in[1];
    const int*   ix = (const int*)d_in[2];
    const float* ml = (const float*)d_in[3];
    const float* cl = (const float*)d_in[4];
    (void)in_sizes; (void)n_in;

    static bool attr_set = false;
    if (!attr_set) {
        cudaFuncSetAttribute(k_main, cudaFuncAttributeMaxDynamicSharedMemorySize,
                             SMEM_BYTES);
        attr_set = true;
    }

    k_zero<<<(NTOT + 255) / 256, 256>>>();
    k_hist<<<BB / 256, 256>>>(ix);
    k_scan<<<1, 1024>>>();
    k_scatter2<<<BB / 256, 256>>>(ix);
    k_sortseg<<<(NTOT + 255) / 256, 256>>>();
    k_mse<<<BB, 128>>>(yp, yt);
    k_aggr<<<BB, 128>>>(yp);
    k_main<<<dim3(BB / TN, BB / TM), 256, SMEM_BYTES>>>(ml, cl);
    k_final<<<1, 1024>>>((float*)d_out, out_size);
}